// round 1
// baseline (speedup 1.0000x reference)
#include <cuda_runtime.h>
#include <math.h>

// Problem constants
#define T_STEPS 1024
#define D_IN    2048
#define NH      2048
#define CATS    1000

// Recurrence kernel config
#define NBLK    128          // persistent blocks (<= SM count, 1 block/SM)
#define NTH     256          // 8 warps
#define NWARP   8
#define RPB     32           // (2*NH)/NBLK rows per block
#define NSTAGE  26           // rows of U pinned in SMEM per block
#define SMEM_FLOATS (NSTAGE*NH + NH)          // staged U rows + p stage
#define SMEM_BYTES  (SMEM_FLOATS * 4)         // 221184 bytes

// Scratch (device globals; no allocation allowed)
__device__ float g_XZ[T_STEPS * NH];
__device__ float g_XH[T_STEPS * NH];
__device__ float g_P[2][NH];
__device__ float g_Z[2][NH];
__device__ float g_HT[2][NH];
__device__ float g_LOGITS[1024];
__device__ unsigned int g_count;   // zero-init; returns to 0 each launch
__device__ unsigned int g_gen;     // monotonically increasing; compared relatively

// ---------------------------------------------------------------------------
// GEMM: C[t, n] = sum_k x[t,k] * W[n,k], n in [0,4096): n<2048 -> Wz -> XZ,
// n>=2048 -> Wh -> XH.  BM=128, BN=64, BK=16, 256 threads, 8x4 microtile.
// ---------------------------------------------------------------------------
#define GBM 128
#define GBN 64
#define GBK 16

__global__ __launch_bounds__(256) void gemm_xproj(
    const float* __restrict__ x,
    const float* __restrict__ Wz,
    const float* __restrict__ Wh)
{
    __shared__ float As[GBK][GBM + 2];   // pad 130 -> conflict-free transposed stores
    __shared__ float Bs[GBK][GBN + 2];   // pad 66

    const int tid  = threadIdx.x;
    const int row0 = blockIdx.y * GBM;   // t tile
    const int col0 = blockIdx.x * GBN;   // n tile (uniform half per block)

    const float* Bbase = (col0 < NH) ? (Wz + (size_t)col0 * D_IN)
                                     : (Wh + (size_t)(col0 - NH) * D_IN);

    const int trow = tid >> 4;           // 0..15
    const int tcol = tid & 15;           // 0..15
    const int m0 = trow * 8;
    const int n0 = tcol * 4;

    float acc[8][4];
    #pragma unroll
    for (int i = 0; i < 8; i++)
        #pragma unroll
        for (int j = 0; j < 4; j++) acc[i][j] = 0.f;

    for (int kt = 0; kt < D_IN; kt += GBK) {
        // A tile: 128 rows x 16 k = 512 float4, 2 per thread
        #pragma unroll
        for (int u = 0; u < 2; u++) {
            int idx = tid + u * 256;
            int ar  = idx >> 2;
            int ac4 = idx & 3;
            float4 v = *(const float4*)(x + (size_t)(row0 + ar) * D_IN + kt + ac4 * 4);
            As[ac4 * 4 + 0][ar] = v.x;
            As[ac4 * 4 + 1][ar] = v.y;
            As[ac4 * 4 + 2][ar] = v.z;
            As[ac4 * 4 + 3][ar] = v.w;
        }
        // B tile: 64 rows x 16 k = 256 float4, 1 per thread
        {
            int br  = tid >> 2;
            int bc4 = tid & 3;
            float4 v = *(const float4*)(Bbase + (size_t)br * D_IN + kt + bc4 * 4);
            Bs[bc4 * 4 + 0][br] = v.x;
            Bs[bc4 * 4 + 1][br] = v.y;
            Bs[bc4 * 4 + 2][br] = v.z;
            Bs[bc4 * 4 + 3][br] = v.w;
        }
        __syncthreads();

        #pragma unroll
        for (int k = 0; k < GBK; k++) {
            float a[8], bb[4];
            #pragma unroll
            for (int i = 0; i < 8; i++) a[i] = As[k][m0 + i];
            #pragma unroll
            for (int j = 0; j < 4; j++) bb[j] = Bs[k][n0 + j];
            #pragma unroll
            for (int i = 0; i < 8; i++)
                #pragma unroll
                for (int j = 0; j < 4; j++) acc[i][j] += a[i] * bb[j];
        }
        __syncthreads();
    }

    // Write out
    #pragma unroll
    for (int i = 0; i < 8; i++) {
        int t = row0 + m0 + i;
        #pragma unroll
        for (int j = 0; j < 4; j++) {
            int n = col0 + n0 + j;
            if (n < NH) g_XZ[(size_t)t * NH + n] = acc[i][j];
            else        g_XH[(size_t)t * NH + (n - NH)] = acc[i][j];
        }
    }
}

// ---------------------------------------------------------------------------
// Grid-wide sense-reversal barrier (all NBLK blocks resident by construction)
// ---------------------------------------------------------------------------
__device__ __forceinline__ void grid_sync()
{
    __syncthreads();
    if (threadIdx.x == 0) {
        volatile unsigned int* genp = &g_gen;
        unsigned int gen = *genp;
        __threadfence();
        if (atomicAdd(&g_count, 1u) == NBLK - 1) {
            g_count = 0;
            __threadfence();
            *genp = gen + 1;
        } else {
            while (*genp == gen) { }
            __threadfence();
        }
    }
    __syncthreads();
}

// ---------------------------------------------------------------------------
// Persistent recurrence kernel. Block b owns output rows R0..R0+31 of the
// concatenated [Uz; Uh] (rows < NH -> z gate, rows >= NH -> htilde).
// NSTAGE rows pinned in SMEM; p held in registers per warp.
// ---------------------------------------------------------------------------
__global__ __launch_bounds__(NTH, 1) void gru_recurrence(
    const float* __restrict__ Uz, const float* __restrict__ Uh,
    const float* __restrict__ bz,
    const float* __restrict__ Wout,
    const float* __restrict__ zt0, const float* __restrict__ htilde0,
    const float* __restrict__ hprev0,
    float* __restrict__ out)
{
    extern __shared__ float sm[];
    float* smU = sm;                 // NSTAGE * NH floats
    float* ps  = sm + NSTAGE * NH;   // NH floats

    const int tid  = threadIdx.x;
    const int w    = tid >> 5;
    const int lane = tid & 31;
    const int b    = blockIdx.x;
    const int R0   = b * RPB;

    // Pin NSTAGE U rows into SMEM (once per launch)
    for (int s = 0; s < NSTAGE; s++) {
        int r = R0 + s;
        const float* src = (r < NH) ? (Uz + (size_t)r * NH) : (Uh + (size_t)(r - NH) * NH);
        for (int i = tid; i < NH / 4; i += NTH)
            ((float4*)(smU + (size_t)s * NH))[i] = ((const float4*)src)[i];
    }

    // Init recurrence state (blocks 0..7 cover 2048 elements)
    {
        int gi = b * NTH + tid;
        if (gi < NH) {
            g_P[0][gi]  = hprev0[gi];
            g_Z[0][gi]  = zt0[gi];
            g_HT[0][gi] = htilde0[gi];
        }
    }
    grid_sync();

    for (int t = 0; t < T_STEPS; t++) {
        const int cur = t & 1, nxt = cur ^ 1;
        const float* Pc = g_P[cur];

        // Stage p into SMEM (bypass L1: written by other SMs last step)
        #pragma unroll
        for (int u = 0; u < 2; u++) {
            int i = tid + u * NTH;
            ((float4*)ps)[i] = __ldcg((const float4*)Pc + i);
        }
        // Elementwise carry update: p' = (1-z)*p + z*ht  (stale gates)
        if (tid < 16) {
            int i = b * 16 + tid;
            float z  = __ldcg(&g_Z[cur][i]);
            float ht = __ldcg(&g_HT[cur][i]);
            float p  = __ldcg(&Pc[i]);
            g_P[nxt][i] = (1.f - z) * p + z * ht;
        }
        __syncthreads();

        // p -> registers (64 regs/lane)
        float4 preg[16];
        #pragma unroll
        for (int j = 0; j < 16; j++) preg[j] = ((const float4*)ps)[j * 32 + lane];

        // 4 matvec rows per warp: s = w + 8*it (balances L2 rows across warps)
        #pragma unroll
        for (int it = 0; it < 4; it++) {
            const int s = w + 8 * it;
            const int r = R0 + s;
            float acc = 0.f;
            if (s < NSTAGE) {
                const float4* u4 = (const float4*)(smU + (size_t)s * NH);
                #pragma unroll
                for (int j = 0; j < 16; j++) {
                    float4 u = u4[j * 32 + lane];
                    acc += u.x * preg[j].x + u.y * preg[j].y
                         + u.z * preg[j].z + u.w * preg[j].w;
                }
            } else {
                const float* src = (r < NH) ? (Uz + (size_t)r * NH)
                                            : (Uh + (size_t)(r - NH) * NH);
                const float4* u4 = (const float4*)src;
                #pragma unroll
                for (int j = 0; j < 16; j++) {
                    float4 u = __ldg(u4 + j * 32 + lane);
                    acc += u.x * preg[j].x + u.y * preg[j].y
                         + u.z * preg[j].z + u.w * preg[j].w;
                }
            }
            #pragma unroll
            for (int off = 16; off; off >>= 1)
                acc += __shfl_xor_sync(0xffffffffu, acc, off);
            if (lane == 0) {
                if (r < NH) {
                    float pre = g_XZ[(size_t)t * NH + r] + acc + __ldg(bz + r);
                    g_Z[nxt][r] = 1.f / (1.f + expf(-pre));
                } else {
                    int rr = r - NH;
                    float pre = g_XH[(size_t)t * NH + rr] + acc;
                    g_HT[nxt][rr] = tanhf(pre);
                }
            }
        }
        grid_sync();
    }

    // h_final = g_P[0]  (T even). Compute logits: 1024 warps cover 1000 rows.
    {
        const float* Pf = g_P[0];
        #pragma unroll
        for (int u = 0; u < 2; u++) {
            int i = tid + u * NTH;
            ((float4*)ps)[i] = __ldcg((const float4*)Pf + i);
        }
        __syncthreads();
        float4 preg[16];
        #pragma unroll
        for (int j = 0; j < 16; j++) preg[j] = ((const float4*)ps)[j * 32 + lane];

        int gw = b * NWARP + w;
        if (gw < CATS) {
            const float4* u4 = (const float4*)(Wout + (size_t)gw * NH);
            float acc = 0.f;
            #pragma unroll
            for (int j = 0; j < 16; j++) {
                float4 u = __ldg(u4 + j * 32 + lane);
                acc += u.x * preg[j].x + u.y * preg[j].y
                     + u.z * preg[j].z + u.w * preg[j].w;
            }
            #pragma unroll
            for (int off = 16; off; off >>= 1)
                acc += __shfl_xor_sync(0xffffffffu, acc, off);
            if (lane == 0) g_LOGITS[gw] = acc;
        }
    }
    grid_sync();

    // Softmax in block 0
    if (b == 0) {
        __shared__ float red[NTH];
        float lm = -1e30f;
        for (int c = tid; c < CATS; c += NTH) lm = fmaxf(lm, __ldcg(&g_LOGITS[c]));
        red[tid] = lm; __syncthreads();
        for (int o = NTH / 2; o; o >>= 1) {
            if (tid < o) red[tid] = fmaxf(red[tid], red[tid + o]);
            __syncthreads();
        }
        float mx = red[0]; __syncthreads();
        float ls = 0.f;
        for (int c = tid; c < CATS; c += NTH) ls += expf(__ldcg(&g_LOGITS[c]) - mx);
        red[tid] = ls; __syncthreads();
        for (int o = NTH / 2; o; o >>= 1) {
            if (tid < o) red[tid] += red[tid + o];
            __syncthreads();
        }
        float inv = 1.f / red[0];
        for (int c = tid; c < CATS; c += NTH)
            out[c] = expf(__ldcg(&g_LOGITS[c]) - mx) * inv;
    }
}

// ---------------------------------------------------------------------------
extern "C" void kernel_launch(void* const* d_in, const int* in_sizes, int n_in,
                              void* d_out, int out_size)
{
    const float* x       = (const float*)d_in[0];
    const float* Wh      = (const float*)d_in[1];
    const float* Wz      = (const float*)d_in[2];
    // d_in[3] = Wr (unused), d_in[7] = Ur (unused), d_in[8] = br (unused)
    const float* Uh      = (const float*)d_in[4];
    const float* Uz      = (const float*)d_in[5];
    const float* bz      = (const float*)d_in[6];
    const float* Wout    = (const float*)d_in[9];
    // d_in[10] = h0 (never read by the reference recurrence)
    const float* zt0     = (const float*)d_in[11];
    const float* htilde0 = (const float*)d_in[12];
    const float* hprev0  = (const float*)d_in[13];
    float* out = (float*)d_out;

    // Input projections (xr is dead code in the reference — skipped)
    dim3 ggrid((NH * 2) / GBN, T_STEPS / GBM);   // (64, 8)
    gemm_xproj<<<ggrid, 256>>>(x, Wz, Wh);

    // Persistent recurrence + logits + softmax
    cudaFuncSetAttribute(gru_recurrence,
                         cudaFuncAttributeMaxDynamicSharedMemorySize, SMEM_BYTES);
    gru_recurrence<<<NBLK, NTH, SMEM_BYTES>>>(Uz, Uh, bz, Wout,
                                              zt0, htilde0, hprev0, out);
}